// round 2
// baseline (speedup 1.0000x reference)
#include <cuda_runtime.h>
#include <math.h>
#include <stdint.h>

// Problem dims (fixed)
#define S_DIM 2048
#define B_DIM 2
#define H_DIM 2048
#define NH_DIM 16
#define D_DIM 128
#define M_DIM 2048
#define FF_DIM 8192
#define ROWS (S_DIM * B_DIM)   // 4096
#define MROWS (M_DIM * B_DIM)  // 4096
#define NBH (B_DIM * NH_DIM)   // 32

// ---------------- scratch (__device__ globals: allocation-free) --------------
__device__ float g_ln[(size_t)ROWS * H_DIM];           // 33.5 MB
__device__ float g_ff[(size_t)ROWS * FF_DIM];          // 134 MB
__device__ float g_x[(size_t)ROWS * H_DIM];            // 33.5 MB
__device__ float g_q[(size_t)ROWS * H_DIM];            // 33.5 MB
__device__ float g_kv[(size_t)MROWS * 2 * H_DIM];      // 67 MB
__device__ float g_ctx[(size_t)ROWS * H_DIM];          // 33.5 MB
__device__ float g_scores[(size_t)NBH * S_DIM * M_DIM];// 537 MB
__device__ int   g_mask_kind;                          // 0 = byte mask, 1 = 4-byte mask

// ---------------- helpers ----------------------------------------------------
__device__ __forceinline__ float gelu_tanh(float v) {
    // JAX default gelu (approximate=True)
    const float c = 0.7978845608028654f;   // sqrt(2/pi)
    float u = c * (v + 0.044715f * v * v * v);
    return 0.5f * v * (1.0f + tanhf(u));
}

// ---------------- mask dtype sniffer -----------------------------------------
// bool mask may arrive as uint8 (1B/elem) or int32/float32 (4B/elem).
// Packed-byte words have bytes in {0,1} -> values like 0x00010001 which are
// never 0, 1, or 0x3F800000. Deterministic on fixed input.
__global__ void detect_mask_kind(const unsigned int* __restrict__ m) {
    if (blockIdx.x == 0 && threadIdx.x == 0) {
        int word_like = 1;
        for (int i = 0; i < 256; ++i) {
            unsigned v = m[i];
            if (v != 0u && v != 1u && v != 0x3F800000u) { word_like = 0; break; }
        }
        g_mask_kind = word_like;
    }
}

// ---------------- GEMM NN: C = act(A*B + bias) [+ R], strided, batched -------
// A: [Mr,K] lda   B: [K,N] ldb   C: [Mr,N] ldc   R optional residual
// Software-pipelined: next k-slab global loads overlap current FFMA block.
template <int ACT>
__global__ void __launch_bounds__(256, 2)
gemm_nn(const float* __restrict__ A, const float* __restrict__ B,
        const float* __restrict__ bias, const float* R, float* C,
        int Mr, int N, int K, int lda, int ldb, int ldc, int ldr,
        long long aBatch, long long bBatch, long long cBatch, long long rBatch)
{
    A += (size_t)blockIdx.z * aBatch;
    B += (size_t)blockIdx.z * bBatch;
    C += (size_t)blockIdx.z * cBatch;
    if (R) R += (size_t)blockIdx.z * rBatch;

    __shared__ float As[8][128];
    __shared__ float Bs[8][128];

    const int tid  = threadIdx.x;
    const int aRow = tid >> 1;          // 0..127
    const int aCol = (tid & 1) << 2;    // 0,4
    const int bRow = tid >> 5;          // 0..7
    const int bCol = (tid & 31) << 2;   // 0..124
    const int tRow = (tid >> 4) << 3;   // 0..120
    const int tCol = (tid & 15) << 3;   // 0..120

    const float* Aptr = A + (size_t)(blockIdx.y * 128 + aRow) * lda + aCol;
    const float* Bptr = B + (size_t)bRow * ldb + blockIdx.x * 128 + bCol;

    float acc[8][8];
    #pragma unroll
    for (int i = 0; i < 8; ++i)
        #pragma unroll
        for (int j = 0; j < 8; ++j) acc[i][j] = 0.f;

    float4 av = *reinterpret_cast<const float4*>(Aptr);
    float4 bv = *reinterpret_cast<const float4*>(Bptr);

    for (int k0 = 0; k0 < K; k0 += 8) {
        As[aCol + 0][aRow] = av.x;
        As[aCol + 1][aRow] = av.y;
        As[aCol + 2][aRow] = av.z;
        As[aCol + 3][aRow] = av.w;
        *reinterpret_cast<float4*>(&Bs[bRow][bCol]) = bv;
        __syncthreads();

        Aptr += 8;
        Bptr += (size_t)8 * ldb;
        const bool more = (k0 + 8 < K);
        if (more) {
            av = *reinterpret_cast<const float4*>(Aptr);
            bv = *reinterpret_cast<const float4*>(Bptr);
        }

        #pragma unroll
        for (int kk = 0; kk < 8; ++kk) {
            float4 a0 = *reinterpret_cast<const float4*>(&As[kk][tRow]);
            float4 a1 = *reinterpret_cast<const float4*>(&As[kk][tRow + 4]);
            float4 b0 = *reinterpret_cast<const float4*>(&Bs[kk][tCol]);
            float4 b1 = *reinterpret_cast<const float4*>(&Bs[kk][tCol + 4]);
            float ar[8] = {a0.x, a0.y, a0.z, a0.w, a1.x, a1.y, a1.z, a1.w};
            float br[8] = {b0.x, b0.y, b0.z, b0.w, b1.x, b1.y, b1.z, b1.w};
            #pragma unroll
            for (int i = 0; i < 8; ++i)
                #pragma unroll
                for (int j = 0; j < 8; ++j)
                    acc[i][j] = fmaf(ar[i], br[j], acc[i][j]);
        }
        __syncthreads();
    }

    #pragma unroll
    for (int i = 0; i < 8; ++i) {
        const int row = blockIdx.y * 128 + tRow + i;
        #pragma unroll
        for (int j = 0; j < 8; ++j) {
            const int col = blockIdx.x * 128 + tCol + j;
            float v = acc[i][j];
            if (bias) v += bias[col];
            if (ACT == 1) v = gelu_tanh(v);
            if (R) v += R[(size_t)row * ldr + col];
            C[(size_t)row * ldc + col] = v;
        }
    }
}

// ---------------- scores = (q . k^T)/sqrt(D), masked -> g_scores -------------
// batched over z = b*NH + h (gridDim.z = 32). K = D = 128.
__global__ void __launch_bounds__(256, 2)
gemm_nt_scores(const float* __restrict__ Q, const float* __restrict__ KV,
               const void* __restrict__ mask, float* __restrict__ C)
{
    const int z = blockIdx.z;
    const float* A  = Q  + (size_t)z * D_DIM;          // q base for (b,h)
    const float* Bm = KV + (size_t)z * 2 * D_DIM;      // k base for (b,h)
    float* Cz = C + (size_t)z * S_DIM * M_DIM;
    const int b = z / NH_DIM;
    const int lda = B_DIM * H_DIM;       // 4096
    const int ldb = B_DIM * 2 * H_DIM;   // 8192

    __shared__ float As[8][128];
    __shared__ float Bs[8][128];

    const int tid  = threadIdx.x;
    const int aRow = tid >> 1;
    const int aCol = (tid & 1) << 2;
    const int tRow = (tid >> 4) << 3;
    const int tCol = (tid & 15) << 3;

    const float* Aptr = A  + (size_t)(blockIdx.y * 128 + aRow) * lda + aCol;
    const float* Bptr = Bm + (size_t)(blockIdx.x * 128 + aRow) * ldb + aCol;

    float acc[8][8];
    #pragma unroll
    for (int i = 0; i < 8; ++i)
        #pragma unroll
        for (int j = 0; j < 8; ++j) acc[i][j] = 0.f;

    float4 av = *reinterpret_cast<const float4*>(Aptr);
    float4 bv = *reinterpret_cast<const float4*>(Bptr);

    for (int k0 = 0; k0 < D_DIM; k0 += 8) {
        As[aCol + 0][aRow] = av.x;
        As[aCol + 1][aRow] = av.y;
        As[aCol + 2][aRow] = av.z;
        As[aCol + 3][aRow] = av.w;
        Bs[aCol + 0][aRow] = bv.x;
        Bs[aCol + 1][aRow] = bv.y;
        Bs[aCol + 2][aRow] = bv.z;
        Bs[aCol + 3][aRow] = bv.w;
        __syncthreads();

        Aptr += 8;
        Bptr += 8;
        const bool more = (k0 + 8 < D_DIM);
        if (more) {
            av = *reinterpret_cast<const float4*>(Aptr);
            bv = *reinterpret_cast<const float4*>(Bptr);
        }

        #pragma unroll
        for (int kk = 0; kk < 8; ++kk) {
            float4 a0 = *reinterpret_cast<const float4*>(&As[kk][tRow]);
            float4 a1 = *reinterpret_cast<const float4*>(&As[kk][tRow + 4]);
            float4 b0 = *reinterpret_cast<const float4*>(&Bs[kk][tCol]);
            float4 b1 = *reinterpret_cast<const float4*>(&Bs[kk][tCol + 4]);
            float ar[8] = {a0.x, a0.y, a0.z, a0.w, a1.x, a1.y, a1.z, a1.w};
            float br[8] = {b0.x, b0.y, b0.z, b0.w, b1.x, b1.y, b1.z, b1.w};
            #pragma unroll
            for (int i = 0; i < 8; ++i)
                #pragma unroll
                for (int j = 0; j < 8; ++j)
                    acc[i][j] = fmaf(ar[i], br[j], acc[i][j]);
        }
        __syncthreads();
    }

    const int maskKind = g_mask_kind;
    const float invNorm = 0.08838834764831845f;  // 1/sqrt(128)

    #pragma unroll
    for (int i = 0; i < 8; ++i) {
        const int s = blockIdx.y * 128 + tRow + i;
        #pragma unroll
        for (int j = 0; j < 8; ++j) {
            const int m = blockIdx.x * 128 + tCol + j;
            const size_t midx = ((size_t)b * S_DIM + s) * M_DIM + m;
            bool masked;
            if (maskKind)
                masked = reinterpret_cast<const unsigned int*>(mask)[midx] != 0u;
            else
                masked = reinterpret_cast<const unsigned char*>(mask)[midx] != 0u;
            Cz[(size_t)s * M_DIM + m] = masked ? -1e4f : acc[i][j] * invNorm;
        }
    }
}

// ---------------- layernorm over rows of H_DIM -------------------------------
__global__ void layernorm_k(const float* __restrict__ x, const float* __restrict__ g,
                            const float* __restrict__ b, float* __restrict__ y)
{
    const int row = blockIdx.x;
    const float* xr = x + (size_t)row * H_DIM;
    float* yr = y + (size_t)row * H_DIM;

    float s = 0.f, ss = 0.f;
    for (int i = threadIdx.x; i < H_DIM; i += blockDim.x) {
        float v = xr[i];
        s += v;
        ss += v * v;
    }
    __shared__ float red[2][32];
    #pragma unroll
    for (int o = 16; o; o >>= 1) {
        s  += __shfl_xor_sync(0xFFFFFFFFu, s, o);
        ss += __shfl_xor_sync(0xFFFFFFFFu, ss, o);
    }
    const int w = threadIdx.x >> 5, l = threadIdx.x & 31;
    if (l == 0) { red[0][w] = s; red[1][w] = ss; }
    __syncthreads();
    if (w == 0) {
        s  = (l < (int)(blockDim.x >> 5)) ? red[0][l] : 0.f;
        ss = (l < (int)(blockDim.x >> 5)) ? red[1][l] : 0.f;
        #pragma unroll
        for (int o = 16; o; o >>= 1) {
            s  += __shfl_xor_sync(0xFFFFFFFFu, s, o);
            ss += __shfl_xor_sync(0xFFFFFFFFu, ss, o);
        }
        if (l == 0) { red[0][0] = s; red[1][0] = ss; }
    }
    __syncthreads();
    const float mu   = red[0][0] * (1.0f / H_DIM);
    const float var  = red[1][0] * (1.0f / H_DIM) - mu * mu;
    const float rstd = rsqrtf(var + 1e-5f);
    for (int i = threadIdx.x; i < H_DIM; i += blockDim.x)
        yr[i] = (xr[i] - mu) * rstd * g[i] + b[i];
}

// ---------------- l2 normalize contiguous rows of 128 ------------------------
__global__ void l2norm_k(float* __restrict__ x, int nrows)
{
    const int row = blockIdx.x * 8 + (threadIdx.x >> 5);
    if (row >= nrows) return;
    const int lane = threadIdx.x & 31;
    float4* p = reinterpret_cast<float4*>(x + (size_t)row * 128) + lane;
    float4 v = *p;
    float s = v.x * v.x + v.y * v.y + v.z * v.z + v.w * v.w;
    #pragma unroll
    for (int o = 16; o; o >>= 1) s += __shfl_xor_sync(0xFFFFFFFFu, s, o);
    const float r = rsqrtf(s + 1e-12f);
    v.x *= r; v.y *= r; v.z *= r; v.w *= r;
    *p = v;
}

// ---------------- softmax over rows of M_DIM (in-place) ----------------------
__global__ void softmax_k(float* __restrict__ x)
{
    __shared__ float buf[M_DIM];
    __shared__ float red[32];
    float* xr = x + (size_t)blockIdx.x * M_DIM;
    const int tid = threadIdx.x;
    const int w = tid >> 5, l = tid & 31;
    const int nw = blockDim.x >> 5;

    float mx = -3.4e38f;
    for (int i = tid; i < M_DIM; i += blockDim.x) {
        float v = xr[i];
        buf[i] = v;
        mx = fmaxf(mx, v);
    }
    #pragma unroll
    for (int o = 16; o; o >>= 1) mx = fmaxf(mx, __shfl_xor_sync(0xFFFFFFFFu, mx, o));
    if (l == 0) red[w] = mx;
    __syncthreads();
    if (w == 0) {
        mx = (l < nw) ? red[l] : -3.4e38f;
        #pragma unroll
        for (int o = 16; o; o >>= 1) mx = fmaxf(mx, __shfl_xor_sync(0xFFFFFFFFu, mx, o));
        if (l == 0) red[0] = mx;
    }
    __syncthreads();
    const float bmax = red[0];
    __syncthreads();

    float sum = 0.f;
    for (int i = tid; i < M_DIM; i += blockDim.x) {
        float e = expf(buf[i] - bmax);
        buf[i] = e;
        sum += e;
    }
    #pragma unroll
    for (int o = 16; o; o >>= 1) sum += __shfl_xor_sync(0xFFFFFFFFu, sum, o);
    if (l == 0) red[w] = sum;
    __syncthreads();
    if (w == 0) {
        sum = (l < nw) ? red[l] : 0.f;
        #pragma unroll
        for (int o = 16; o; o >>= 1) sum += __shfl_xor_sync(0xFFFFFFFFu, sum, o);
        if (l == 0) red[0] = sum;
    }
    __syncthreads();
    const float inv = 1.0f / red[0];
    for (int i = tid; i < M_DIM; i += blockDim.x)
        xr[i] = buf[i] * inv;
}

// ---------------- launcher ---------------------------------------------------
extern "C" void kernel_launch(void* const* d_in, const int* in_sizes, int n_in,
                              void* d_out, int out_size)
{
    const float* x        = (const float*)d_in[0];
    const float* mem      = (const float*)d_in[1];
    const void*  mask     = d_in[2];
    const float* ln1_g    = (const float*)d_in[3];
    const float* ln1_b    = (const float*)d_in[4];
    const float* ln2_g    = (const float*)d_in[5];
    const float* ln2_b    = (const float*)d_in[6];
    const float* ln3_g    = (const float*)d_in[7];
    const float* ln3_b    = (const float*)d_in[8];
    const float* w_mlp1i  = (const float*)d_in[9];
    const float* b_mlp1i  = (const float*)d_in[10];
    const float* w_mlp1o  = (const float*)d_in[11];
    const float* b_mlp1o  = (const float*)d_in[12];
    const float* w_q      = (const float*)d_in[13];
    const float* b_q      = (const float*)d_in[14];
    const float* w_kv     = (const float*)d_in[15];
    const float* b_kv     = (const float*)d_in[16];
    const float* w_dense  = (const float*)d_in[17];
    const float* b_dense  = (const float*)d_in[18];
    const float* w_mlp2i  = (const float*)d_in[19];
    const float* b_mlp2i  = (const float*)d_in[20];
    const float* w_mlp2o  = (const float*)d_in[21];
    const float* b_mlp2o  = (const float*)d_in[22];
    float* out = (float*)d_out;

    float *p_ln, *p_ff, *p_x, *p_q, *p_kv, *p_ctx, *p_sc;
    cudaGetSymbolAddress((void**)&p_ln,  g_ln);
    cudaGetSymbolAddress((void**)&p_ff,  g_ff);
    cudaGetSymbolAddress((void**)&p_x,   g_x);
    cudaGetSymbolAddress((void**)&p_q,   g_q);
    cudaGetSymbolAddress((void**)&p_kv,  g_kv);
    cudaGetSymbolAddress((void**)&p_ctx, g_ctx);
    cudaGetSymbolAddress((void**)&p_sc,  g_scores);

    detect_mask_kind<<<1, 32>>>((const unsigned int*)mask);

    // x = MLP1(LN1(x))   (no residual!)
    layernorm_k<<<ROWS, 256>>>(x, ln1_g, ln1_b, p_ln);
    gemm_nn<1><<<dim3(FF_DIM / 128, ROWS / 128, 1), 256>>>(
        p_ln, w_mlp1i, b_mlp1i, nullptr, p_ff,
        ROWS, FF_DIM, H_DIM, H_DIM, FF_DIM, FF_DIM, 0, 0, 0, 0, 0);
    gemm_nn<0><<<dim3(H_DIM / 128, ROWS / 128, 1), 256>>>(
        p_ff, w_mlp1o, b_mlp1o, nullptr, p_x,
        ROWS, H_DIM, FF_DIM, FF_DIM, H_DIM, H_DIM, 0, 0, 0, 0, 0);

    // q = l2(LN2(x) @ w_q + b_q)
    layernorm_k<<<ROWS, 256>>>(p_x, ln2_g, ln2_b, p_ln);
    gemm_nn<0><<<dim3(H_DIM / 128, ROWS / 128, 1), 256>>>(
        p_ln, w_q, b_q, nullptr, p_q,
        ROWS, H_DIM, H_DIM, H_DIM, H_DIM, H_DIM, 0, 0, 0, 0, 0);
    l2norm_k<<<(ROWS * NH_DIM) / 8, 256>>>(p_q, ROWS * NH_DIM);

    // kv = mem @ w_kv + b_kv ; l2-normalize each 128-wide segment (k and v)
    gemm_nn<0><<<dim3(2 * H_DIM / 128, MROWS / 128, 1), 256>>>(
        mem, w_kv, b_kv, nullptr, p_kv,
        MROWS, 2 * H_DIM, H_DIM, H_DIM, 2 * H_DIM, 2 * H_DIM, 0, 0, 0, 0, 0);
    l2norm_k<<<(MROWS * NH_DIM * 2) / 8, 256>>>(p_kv, MROWS * NH_DIM * 2);

    // scores + mask, softmax, ctx = P @ v
    gemm_nt_scores<<<dim3(M_DIM / 128, S_DIM / 128, NBH), 256>>>(p_q, p_kv, mask, p_sc);
    softmax_k<<<NBH * S_DIM, 256>>>(p_sc);
    gemm_nn<0><<<dim3(1, S_DIM / 128, NBH), 256>>>(
        p_sc, p_kv + D_DIM, nullptr, nullptr, p_ctx,
        S_DIM, D_DIM, M_DIM,
        M_DIM, B_DIM * 2 * H_DIM, B_DIM * H_DIM, 0,
        (long long)S_DIM * M_DIM, 2 * D_DIM, D_DIM, 0);

    // x = x + ctx @ w_dense + b_dense (in-place residual)
    gemm_nn<0><<<dim3(H_DIM / 128, ROWS / 128, 1), 256>>>(
        p_ctx, w_dense, b_dense, p_x, p_x,
        ROWS, H_DIM, H_DIM, H_DIM, H_DIM, H_DIM, H_DIM, 0, 0, 0, 0);

    // out = x + MLP2(LN3(x))
    layernorm_k<<<ROWS, 256>>>(p_x, ln3_g, ln3_b, p_ln);
    gemm_nn<1><<<dim3(FF_DIM / 128, ROWS / 128, 1), 256>>>(
        p_ln, w_mlp2i, b_mlp2i, nullptr, p_ff,
        ROWS, FF_DIM, H_DIM, H_DIM, FF_DIM, FF_DIM, 0, 0, 0, 0, 0);
    gemm_nn<0><<<dim3(H_DIM / 128, ROWS / 128, 1), 256>>>(
        p_ff, w_mlp2o, b_mlp2o, p_x, out,
        ROWS, H_DIM, FF_DIM, FF_DIM, H_DIM, H_DIM, H_DIM, 0, 0, 0, 0);
}

// round 4
// speedup vs baseline: 1.8175x; 1.8175x over previous
#include <cuda_runtime.h>
#include <cuda_bf16.h>
#include <math.h>
#include <stdint.h>

// Problem dims (fixed)
#define S_DIM 2048
#define B_DIM 2
#define H_DIM 2048
#define NH_DIM 16
#define D_DIM 128
#define M_DIM 2048
#define FF_DIM 8192
#define ROWS (S_DIM * B_DIM)   // 4096
#define MROWS (M_DIM * B_DIM)  // 4096
#define NBH (B_DIM * NH_DIM)   // 32

// ---------------- scratch (__device__ globals: allocation-free) --------------
__device__ __align__(256) float g_ln[(size_t)ROWS * H_DIM];
__device__ __align__(256) float g_ff[(size_t)ROWS * FF_DIM];
__device__ __align__(256) float g_x[(size_t)ROWS * H_DIM];
__device__ __align__(256) float g_q[(size_t)ROWS * H_DIM];
__device__ __align__(256) float g_kv[(size_t)MROWS * 2 * H_DIM];
__device__ __align__(256) float g_ctx[(size_t)ROWS * H_DIM];
__device__ __align__(256) float g_scores[(size_t)NBH * S_DIM * M_DIM];
__device__ int g_mask_kind;
#define ABF_CAP ((size_t)4096 * 8192)
#define BBF_CAP ((size_t)8192 * 2048)
__device__ __align__(256) __nv_bfloat16 g_abf[2 * ABF_CAP];  // hi | lo
__device__ __align__(256) __nv_bfloat16 g_bbf[2 * BBF_CAP];  // hi | lo

// ---------------- helpers ----------------------------------------------------
__device__ __forceinline__ float gelu_tanh(float v) {
    const float c = 0.7978845608028654f;   // sqrt(2/pi)
    float u = c * (v + 0.044715f * v * v * v);
    return 0.5f * v * (1.0f + tanhf(u));
}

__device__ __forceinline__ uint32_t smem_u32(const void* p) {
    uint32_t a;
    asm("{ .reg .u64 t; cvta.to.shared.u64 t, %1; cvt.u32.u64 %0, t; }" : "=r"(a) : "l"(p));
    return a;
}

__device__ __forceinline__ void cp16(uint32_t saddr, const void* gaddr) {
    asm volatile("cp.async.cg.shared.global [%0], [%1], 16;" :: "r"(saddr), "l"(gaddr));
}
__device__ __forceinline__ void cp_commit() {
    asm volatile("cp.async.commit_group;" ::: "memory");
}
template <int N>
__device__ __forceinline__ void cp_wait() {
    asm volatile("cp.async.wait_group %0;" :: "n"(N) : "memory");
}

__device__ __forceinline__ uint32_t lds32(uint32_t a) {
    uint32_t v;
    asm volatile("ld.shared.b32 %0, [%1];" : "=r"(v) : "r"(a));
    return v;
}

__device__ __forceinline__ void mma16816(float* c, const uint32_t* a, const uint32_t* b) {
    asm volatile(
        "mma.sync.aligned.m16n8k16.row.col.f32.bf16.bf16.f32 "
        "{%0,%1,%2,%3}, {%4,%5,%6,%7}, {%8,%9}, {%0,%1,%2,%3};"
        : "+f"(c[0]), "+f"(c[1]), "+f"(c[2]), "+f"(c[3])
        : "r"(a[0]), "r"(a[1]), "r"(a[2]), "r"(a[3]), "r"(b[0]), "r"(b[1]));
}

// ---------------- operand split kernels --------------------------------------
__global__ void cvt_hl(const float4* __restrict__ in, uint2* __restrict__ hi,
                       uint2* __restrict__ lo, size_t n4)
{
    size_t i = blockIdx.x * (size_t)blockDim.x + threadIdx.x;
    if (i >= n4) return;
    float4 v = in[i];
    __nv_bfloat16 h0 = __float2bfloat16(v.x), h1 = __float2bfloat16(v.y);
    __nv_bfloat16 h2 = __float2bfloat16(v.z), h3 = __float2bfloat16(v.w);
    __nv_bfloat16 l0 = __float2bfloat16(v.x - __bfloat162float(h0));
    __nv_bfloat16 l1 = __float2bfloat16(v.y - __bfloat162float(h1));
    __nv_bfloat16 l2 = __float2bfloat16(v.z - __bfloat162float(h2));
    __nv_bfloat16 l3 = __float2bfloat16(v.w - __bfloat162float(h3));
    uint2 H, L;
    H.x = ((uint32_t)__bfloat16_as_ushort(h1) << 16) | __bfloat16_as_ushort(h0);
    H.y = ((uint32_t)__bfloat16_as_ushort(h3) << 16) | __bfloat16_as_ushort(h2);
    L.x = ((uint32_t)__bfloat16_as_ushort(l1) << 16) | __bfloat16_as_ushort(l0);
    L.y = ((uint32_t)__bfloat16_as_ushort(l3) << 16) | __bfloat16_as_ushort(l2);
    hi[i] = H;
    lo[i] = L;
}

// weight transpose + split: fp32 [K,N] -> hi/lo bf16 [N,K]
__global__ void cvt_wt_t(const float* __restrict__ in, int K, int N,
                         __nv_bfloat16* __restrict__ hi, __nv_bfloat16* __restrict__ lo)
{
    __shared__ float t[32][33];
    const int k0 = blockIdx.y << 5;
    const int n0 = blockIdx.x << 5;
    const int tx = threadIdx.x, ty = threadIdx.y;
    #pragma unroll
    for (int i = ty; i < 32; i += 8)
        t[i][tx] = in[(size_t)(k0 + i) * N + n0 + tx];
    __syncthreads();
    #pragma unroll
    for (int i = ty; i < 32; i += 8) {
        float v = t[tx][i];
        __nv_bfloat16 h = __float2bfloat16(v);
        size_t o = (size_t)(n0 + i) * K + k0 + tx;
        hi[o] = h;
        lo[o] = __float2bfloat16(v - __bfloat162float(h));
    }
}

// ---------------- mma.sync GEMM: C[Mr,N]=act(Ahl x Bhl^T + bias)[+R] ---------
// A split [rows,K] K-contig; B split [N,K] K-contig. 128x128 tile, BK=32.
// SMEM per stage: 4 matrices x [128][40] bf16 (stride 40 elems = conflict-free)
#define MM_STRIDE_B 80                 // 40 elems * 2B
#define MM_MAT (128 * MM_STRIDE_B)     // 10240 B
#define MM_STAGE (4 * MM_MAT)          // 40960 B
#define MM_SMEM (2 * MM_STAGE)         // 81920 B

template <int ACT>
__global__ void __launch_bounds__(256, 1)
gemm_mma(const __nv_bfloat16* __restrict__ Ah, const __nv_bfloat16* __restrict__ Al,
         const __nv_bfloat16* __restrict__ Bh, const __nv_bfloat16* __restrict__ Bl,
         const float* __restrict__ bias, const float* R, float* C, int K, int ldc)
{
    extern __shared__ char sm[];
    const uint32_t sbase = smem_u32(sm);
    const int tid = threadIdx.x;
    const int wid = tid >> 5, lane = tid & 31;
    const int m0 = blockIdx.y * 128, n0 = blockIdx.x * 128;
    const int wm = wid >> 2, wn = wid & 3;        // 2x4 warp grid
    const int g = lane >> 2, ti = lane & 3;

    float acc[4][4][4];
    #pragma unroll
    for (int a = 0; a < 4; ++a)
        #pragma unroll
        for (int b = 0; b < 4; ++b)
            #pragma unroll
            for (int c = 0; c < 4; ++c) acc[a][b][c] = 0.f;

    // per-thread load assignment: 512 16B-chunks per matrix, 2 per thread
    const int r0 = tid >> 2, ch0 = tid & 3;       // chunk set 0: rows 0..63
    // chunk set 1: c = tid + 256 -> rows 64..127, same ch
    auto load_stage = [&](int buf, int k0) {
        const uint32_t st = sbase + buf * MM_STAGE;
        #pragma unroll
        for (int i = 0; i < 2; ++i) {
            const int row = r0 + i * 64;
            const uint32_t d = st + row * MM_STRIDE_B + ch0 * 16;
            const size_t ga = (size_t)(m0 + row) * K + k0 + ch0 * 8;
            const size_t gb = (size_t)(n0 + row) * K + k0 + ch0 * 8;
            cp16(d + 0 * MM_MAT, Ah + ga);
            cp16(d + 1 * MM_MAT, Al + ga);
            cp16(d + 2 * MM_MAT, Bh + gb);
            cp16(d + 3 * MM_MAT, Bl + gb);
        }
        cp_commit();
    };

    load_stage(0, 0);
    const int S = K >> 5;

    for (int s = 0; s < S; ++s) {
        if (s + 1 < S) {
            load_stage((s + 1) & 1, (s + 1) << 5);
            cp_wait<1>();
        } else {
            cp_wait<0>();
        }
        __syncthreads();

        const uint32_t st = sbase + (s & 1) * MM_STAGE;
        #pragma unroll
        for (int ks = 0; ks < 2; ++ks) {
            const uint32_t kb = ks * 32 + ti * 4;   // byte offset of k within row
            uint32_t ah[4][4], al[4][4], bh[4][2], bl[4][2];
            #pragma unroll
            for (int mt = 0; mt < 4; ++mt) {
                const uint32_t ra = st + (wm * 64 + mt * 16 + g) * MM_STRIDE_B + kb;
                ah[mt][0] = lds32(ra);
                ah[mt][1] = lds32(ra + 8 * MM_STRIDE_B);
                ah[mt][2] = lds32(ra + 16);
                ah[mt][3] = lds32(ra + 8 * MM_STRIDE_B + 16);
                const uint32_t rl = ra + MM_MAT;
                al[mt][0] = lds32(rl);
                al[mt][1] = lds32(rl + 8 * MM_STRIDE_B);
                al[mt][2] = lds32(rl + 16);
                al[mt][3] = lds32(rl + 8 * MM_STRIDE_B + 16);
            }
            #pragma unroll
            for (int nt = 0; nt < 4; ++nt) {
                const uint32_t rb = st + 2 * MM_MAT + (wn * 32 + nt * 8 + g) * MM_STRIDE_B + kb;
                bh[nt][0] = lds32(rb);
                bh[nt][1] = lds32(rb + 16);
                bl[nt][0] = lds32(rb + MM_MAT);
                bl[nt][1] = lds32(rb + MM_MAT + 16);
            }
            #pragma unroll
            for (int mt = 0; mt < 4; ++mt)
                #pragma unroll
                for (int nt = 0; nt < 4; ++nt)
                    mma16816(acc[mt][nt], ah[mt], bh[nt]);
            #pragma unroll
            for (int mt = 0; mt < 4; ++mt)
                #pragma unroll
                for (int nt = 0; nt < 4; ++nt)
                    mma16816(acc[mt][nt], al[mt], bh[nt]);
            #pragma unroll
            for (int mt = 0; mt < 4; ++mt)
                #pragma unroll
                for (int nt = 0; nt < 4; ++nt)
                    mma16816(acc[mt][nt], ah[mt], bl[nt]);
        }
        __syncthreads();
    }

    // epilogue
    #pragma unroll
    for (int mt = 0; mt < 4; ++mt) {
        const int r = m0 + wm * 64 + mt * 16 + g;
        #pragma unroll
        for (int nt = 0; nt < 4; ++nt) {
            const int c = n0 + wn * 32 + nt * 8 + ti * 2;
            float v0 = acc[mt][nt][0], v1 = acc[mt][nt][1];
            float v2 = acc[mt][nt][2], v3 = acc[mt][nt][3];
            if (bias) {
                const float b0 = bias[c], b1 = bias[c + 1];
                v0 += b0; v1 += b1; v2 += b0; v3 += b1;
            }
            if (ACT == 1) {
                v0 = gelu_tanh(v0); v1 = gelu_tanh(v1);
                v2 = gelu_tanh(v2); v3 = gelu_tanh(v3);
            }
            if (R) {
                v0 += R[(size_t)r * ldc + c];
                v1 += R[(size_t)r * ldc + c + 1];
                v2 += R[(size_t)(r + 8) * ldc + c];
                v3 += R[(size_t)(r + 8) * ldc + c + 1];
            }
            C[(size_t)r * ldc + c]           = v0;
            C[(size_t)r * ldc + c + 1]       = v1;
            C[(size_t)(r + 8) * ldc + c]     = v2;
            C[(size_t)(r + 8) * ldc + c + 1] = v3;
        }
    }
}

// ---------------- mask dtype sniffer -----------------------------------------
__global__ void detect_mask_kind(const unsigned int* __restrict__ m) {
    if (blockIdx.x == 0 && threadIdx.x == 0) {
        int word_like = 1;
        for (int i = 0; i < 256; ++i) {
            unsigned v = m[i];
            if (v != 0u && v != 1u && v != 0x3F800000u) { word_like = 0; break; }
        }
        g_mask_kind = word_like;
    }
}

// ---------------- SIMT GEMM NN (ctx = probs @ v) -----------------------------
template <int ACT>
__global__ void __launch_bounds__(256, 2)
gemm_nn(const float* __restrict__ A, const float* __restrict__ B,
        const float* __restrict__ bias, const float* R, float* C,
        int Mr, int N, int K, int lda, int ldb, int ldc, int ldr,
        long long aBatch, long long bBatch, long long cBatch, long long rBatch)
{
    A += (size_t)blockIdx.z * aBatch;
    B += (size_t)blockIdx.z * bBatch;
    C += (size_t)blockIdx.z * cBatch;
    if (R) R += (size_t)blockIdx.z * rBatch;

    __shared__ float As[8][128];
    __shared__ float Bs[8][128];

    const int tid  = threadIdx.x;
    const int aRow = tid >> 1;
    const int aCol = (tid & 1) << 2;
    const int bRow = tid >> 5;
    const int bCol = (tid & 31) << 2;
    const int tRow = (tid >> 4) << 3;
    const int tCol = (tid & 15) << 3;

    const float* Aptr = A + (size_t)(blockIdx.y * 128 + aRow) * lda + aCol;
    const float* Bptr = B + (size_t)bRow * ldb + blockIdx.x * 128 + bCol;

    float acc[8][8];
    #pragma unroll
    for (int i = 0; i < 8; ++i)
        #pragma unroll
        for (int j = 0; j < 8; ++j) acc[i][j] = 0.f;

    float4 av = *reinterpret_cast<const float4*>(Aptr);
    float4 bv = *reinterpret_cast<const float4*>(Bptr);

    for (int k0 = 0; k0 < K; k0 += 8) {
        As[aCol + 0][aRow] = av.x;
        As[aCol + 1][aRow] = av.y;
        As[aCol + 2][aRow] = av.z;
        As[aCol + 3][aRow] = av.w;
        *reinterpret_cast<float4*>(&Bs[bRow][bCol]) = bv;
        __syncthreads();

        Aptr += 8;
        Bptr += (size_t)8 * ldb;
        if (k0 + 8 < K) {
            av = *reinterpret_cast<const float4*>(Aptr);
            bv = *reinterpret_cast<const float4*>(Bptr);
        }

        #pragma unroll
        for (int kk = 0; kk < 8; ++kk) {
            float4 a0 = *reinterpret_cast<const float4*>(&As[kk][tRow]);
            float4 a1 = *reinterpret_cast<const float4*>(&As[kk][tRow + 4]);
            float4 b0 = *reinterpret_cast<const float4*>(&Bs[kk][tCol]);
            float4 b1 = *reinterpret_cast<const float4*>(&Bs[kk][tCol + 4]);
            float ar[8] = {a0.x, a0.y, a0.z, a0.w, a1.x, a1.y, a1.z, a1.w};
            float br[8] = {b0.x, b0.y, b0.z, b0.w, b1.x, b1.y, b1.z, b1.w};
            #pragma unroll
            for (int i = 0; i < 8; ++i)
                #pragma unroll
                for (int j = 0; j < 8; ++j)
                    acc[i][j] = fmaf(ar[i], br[j], acc[i][j]);
        }
        __syncthreads();
    }

    #pragma unroll
    for (int i = 0; i < 8; ++i) {
        const int row = blockIdx.y * 128 + tRow + i;
        #pragma unroll
        for (int j = 0; j < 8; ++j) {
            const int col = blockIdx.x * 128 + tCol + j;
            float v = acc[i][j];
            if (bias) v += bias[col];
            if (ACT == 1) v = gelu_tanh(v);
            if (R) v += R[(size_t)row * ldr + col];
            C[(size_t)row * ldc + col] = v;
        }
    }
}

// ---------------- scores = (q.k^T)/sqrt(D), masked ---------------------------
__global__ void __launch_bounds__(256, 2)
gemm_nt_scores(const float* __restrict__ Q, const float* __restrict__ KV,
               const void* __restrict__ mask, float* __restrict__ C)
{
    const int z = blockIdx.z;
    const float* A  = Q  + (size_t)z * D_DIM;
    const float* Bm = KV + (size_t)z * 2 * D_DIM;
    float* Cz = C + (size_t)z * S_DIM * M_DIM;
    const int b = z / NH_DIM;
    const int lda = B_DIM * H_DIM;
    const int ldb = B_DIM * 2 * H_DIM;

    __shared__ float As[8][128];
    __shared__ float Bs[8][128];

    const int tid  = threadIdx.x;
    const int aRow = tid >> 1;
    const int aCol = (tid & 1) << 2;
    const int tRow = (tid >> 4) << 3;
    const int tCol = (tid & 15) << 3;

    const float* Aptr = A  + (size_t)(blockIdx.y * 128 + aRow) * lda + aCol;
    const float* Bptr = Bm + (size_t)(blockIdx.x * 128 + aRow) * ldb + aCol;

    float acc[8][8];
    #pragma unroll
    for (int i = 0; i < 8; ++i)
        #pragma unroll
        for (int j = 0; j < 8; ++j) acc[i][j] = 0.f;

    float4 av = *reinterpret_cast<const float4*>(Aptr);
    float4 bv = *reinterpret_cast<const float4*>(Bptr);

    for (int k0 = 0; k0 < D_DIM; k0 += 8) {
        As[aCol + 0][aRow] = av.x;
        As[aCol + 1][aRow] = av.y;
        As[aCol + 2][aRow] = av.z;
        As[aCol + 3][aRow] = av.w;
        Bs[aCol + 0][aRow] = bv.x;
        Bs[aCol + 1][aRow] = bv.y;
        Bs[aCol + 2][aRow] = bv.z;
        Bs[aCol + 3][aRow] = bv.w;
        __syncthreads();

        Aptr += 8;
        Bptr += 8;
        if (k0 + 8 < D_DIM) {
            av = *reinterpret_cast<const float4*>(Aptr);
            bv = *reinterpret_cast<const float4*>(Bptr);
        }

        #pragma unroll
        for (int kk = 0; kk < 8; ++kk) {
            float4 a0 = *reinterpret_cast<const float4*>(&As[kk][tRow]);
            float4 a1 = *reinterpret_cast<const float4*>(&As[kk][tRow + 4]);
            float4 b0 = *reinterpret_cast<const float4*>(&Bs[kk][tCol]);
            float4 b1 = *reinterpret_cast<const float4*>(&Bs[kk][tCol + 4]);
            float ar[8] = {a0.x, a0.y, a0.z, a0.w, a1.x, a1.y, a1.z, a1.w};
            float br[8] = {b0.x, b0.y, b0.z, b0.w, b1.x, b1.y, b1.z, b1.w};
            #pragma unroll
            for (int i = 0; i < 8; ++i)
                #pragma unroll
                for (int j = 0; j < 8; ++j)
                    acc[i][j] = fmaf(ar[i], br[j], acc[i][j]);
        }
        __syncthreads();
    }

    const int maskKind = g_mask_kind;
    const float invNorm = 0.08838834764831845f;

    #pragma unroll
    for (int i = 0; i < 8; ++i) {
        const int s = blockIdx.y * 128 + tRow + i;
        #pragma unroll
        for (int j = 0; j < 8; ++j) {
            const int m = blockIdx.x * 128 + tCol + j;
            const size_t midx = ((size_t)b * S_DIM + s) * M_DIM + m;
            bool masked;
            if (maskKind)
                masked = reinterpret_cast<const unsigned int*>(mask)[midx] != 0u;
            else
                masked = reinterpret_cast<const unsigned char*>(mask)[midx] != 0u;
            Cz[(size_t)s * M_DIM + m] = masked ? -1e4f : acc[i][j] * invNorm;
        }
    }
}

// ---------------- layernorm --------------------------------------------------
__global__ void layernorm_k(const float* __restrict__ x, const float* __restrict__ g,
                            const float* __restrict__ b, float* __restrict__ y)
{
    const int row = blockIdx.x;
    const float* xr = x + (size_t)row * H_DIM;
    float* yr = y + (size_t)row * H_DIM;

    float s = 0.f, ss = 0.f;
    for (int i = threadIdx.x; i < H_DIM; i += blockDim.x) {
        float v = xr[i];
        s += v;
        ss += v * v;
    }
    __shared__ float red[2][32];
    #pragma unroll
    for (int o = 16; o; o >>= 1) {
        s  += __shfl_xor_sync(0xFFFFFFFFu, s, o);
        ss += __shfl_xor_sync(0xFFFFFFFFu, ss, o);
    }
    const int w = threadIdx.x >> 5, l = threadIdx.x & 31;
    if (l == 0) { red[0][w] = s; red[1][w] = ss; }
    __syncthreads();
    if (w == 0) {
        s  = (l < (int)(blockDim.x >> 5)) ? red[0][l] : 0.f;
        ss = (l < (int)(blockDim.x >> 5)) ? red[1][l] : 0.f;
        #pragma unroll
        for (int o = 16; o; o >>= 1) {
            s  += __shfl_xor_sync(0xFFFFFFFFu, s, o);
            ss += __shfl_xor_sync(0xFFFFFFFFu, ss, o);
        }
        if (l == 0) { red[0][0] = s; red[1][0] = ss; }
    }
    __syncthreads();
    const float mu   = red[0][0] * (1.0f / H_DIM);
    const float var  = red[1][0] * (1.0f / H_DIM) - mu * mu;
    const float rstd = rsqrtf(var + 1e-5f);
    for (int i = threadIdx.x; i < H_DIM; i += blockDim.x)
        yr[i] = (xr[i] - mu) * rstd * g[i] + b[i];
}

// ---------------- l2 normalize rows of 128 -----------------------------------
__global__ void l2norm_k(float* __restrict__ x, int nrows)
{
    const int row = blockIdx.x * 8 + (threadIdx.x >> 5);
    if (row >= nrows) return;
    const int lane = threadIdx.x & 31;
    float4* p = reinterpret_cast<float4*>(x + (size_t)row * 128) + lane;
    float4 v = *p;
    float s = v.x * v.x + v.y * v.y + v.z * v.z + v.w * v.w;
    #pragma unroll
    for (int o = 16; o; o >>= 1) s += __shfl_xor_sync(0xFFFFFFFFu, s, o);
    const float r = rsqrtf(s + 1e-12f);
    v.x *= r; v.y *= r; v.z *= r; v.w *= r;
    *p = v;
}

// ---------------- softmax over rows of M_DIM ---------------------------------
__global__ void softmax_k(float* __restrict__ x)
{
    __shared__ float buf[M_DIM];
    __shared__ float red[32];
    float* xr = x + (size_t)blockIdx.x * M_DIM;
    const int tid = threadIdx.x;
    const int w = tid >> 5, l = tid & 31;
    const int nw = blockDim.x >> 5;

    float mx = -3.4e38f;
    for (int i = tid; i < M_DIM; i += blockDim.x) {
        float v = xr[i];
        buf[i] = v;
        mx = fmaxf(mx, v);
    }
    #pragma unroll
    for (int o = 16; o; o >>= 1) mx = fmaxf(mx, __shfl_xor_sync(0xFFFFFFFFu, mx, o));
    if (l == 0) red[w] = mx;
    __syncthreads();
    if (w == 0) {
        mx = (l < nw) ? red[l] : -3.4e38f;
        #pragma unroll
        for (int o = 16; o; o >>= 1) mx = fmaxf(mx, __shfl_xor_sync(0xFFFFFFFFu, mx, o));
        if (l == 0) red[0] = mx;
    }
    __syncthreads();
    const float bmax = red[0];
    __syncthreads();

    float sum = 0.f;
    for (int i = tid; i < M_DIM; i += blockDim.x) {
        float e = expf(buf[i] - bmax);
        buf[i] = e;
        sum += e;
    }
    #pragma unroll
    for (int o = 16; o; o >>= 1) sum += __shfl_xor_sync(0xFFFFFFFFu, sum, o);
    if (l == 0) red[w] = sum;
    __syncthreads();
    if (w == 0) {
        sum = (l < nw) ? red[l] : 0.f;
        #pragma unroll
        for (int o = 16; o; o >>= 1) sum += __shfl_xor_sync(0xFFFFFFFFu, sum, o);
        if (l == 0) red[0] = sum;
    }
    __syncthreads();
    const float inv = 1.0f / red[0];
    for (int i = tid; i < M_DIM; i += blockDim.x)
        xr[i] = buf[i] * inv;
}

// ---------------- launcher ---------------------------------------------------
static void run_mm(int act, const __nv_bfloat16* aHi, const __nv_bfloat16* aLo,
                   const __nv_bfloat16* bHi, const __nv_bfloat16* bLo,
                   const float* bias, const float* R, float* C, int K, int N)
{
    dim3 grid(N / 128, ROWS / 128);
    if (act)
        gemm_mma<1><<<grid, 256, MM_SMEM>>>(aHi, aLo, bHi, bLo, bias, R, C, K, N);
    else
        gemm_mma<0><<<grid, 256, MM_SMEM>>>(aHi, aLo, bHi, bLo, bias, R, C, K, N);
}

extern "C" void kernel_launch(void* const* d_in, const int* in_sizes, int n_in,
                              void* d_out, int out_size)
{
    const float* x        = (const float*)d_in[0];
    const float* mem      = (const float*)d_in[1];
    const void*  mask     = d_in[2];
    const float* ln1_g    = (const float*)d_in[3];
    const float* ln1_b    = (const float*)d_in[4];
    const float* ln2_g    = (const float*)d_in[5];
    const float* ln2_b    = (const float*)d_in[6];
    const float* ln3_g    = (const float*)d_in[7];
    const float* ln3_b    = (const float*)d_in[8];
    const float* w_mlp1i  = (const float*)d_in[9];
    const float* b_mlp1i  = (const float*)d_in[10];
    const float* w_mlp1o  = (const float*)d_in[11];
    const float* b_mlp1o  = (const float*)d_in[12];
    const float* w_q      = (const float*)d_in[13];
    const float* b_q      = (const float*)d_in[14];
    const float* w_kv     = (const float*)d_in[15];
    const float* b_kv     = (const float*)d_in[16];
    const float* w_dense  = (const float*)d_in[17];
    const float* b_dense  = (const float*)d_in[18];
    const float* w_mlp2i  = (const float*)d_in[19];
    const float* b_mlp2i  = (const float*)d_in[20];
    const float* w_mlp2o  = (const float*)d_in[21];
    const float* b_mlp2o  = (const float*)d_in[22];
    float* out = (float*)d_out;

    cudaFuncSetAttribute(gemm_mma<0>, cudaFuncAttributeMaxDynamicSharedMemorySize, MM_SMEM);
    cudaFuncSetAttribute(gemm_mma<1>, cudaFuncAttributeMaxDynamicSharedMemorySize, MM_SMEM);

    float *p_ln, *p_ff, *p_x, *p_q, *p_kv, *p_ctx, *p_sc;
    __nv_bfloat16 *pA, *pB;
    cudaGetSymbolAddress((void**)&p_ln,  g_ln);
    cudaGetSymbolAddress((void**)&p_ff,  g_ff);
    cudaGetSymbolAddress((void**)&p_x,   g_x);
    cudaGetSymbolAddress((void**)&p_q,   g_q);
    cudaGetSymbolAddress((void**)&p_kv,  g_kv);
    cudaGetSymbolAddress((void**)&p_ctx, g_ctx);
    cudaGetSymbolAddress((void**)&p_sc,  g_scores);
    cudaGetSymbolAddress((void**)&pA,    g_abf);
    cudaGetSymbolAddress((void**)&pB,    g_bbf);
    __nv_bfloat16 *aHi = pA, *aLo = pA + ABF_CAP;
    __nv_bfloat16 *bHi = pB, *bLo = pB + BBF_CAP;

    auto cvtA = [&](const float* src, size_t n) {
        size_t n4 = n >> 2;
        cvt_hl<<<(unsigned)((n4 + 255) / 256), 256>>>(
            (const float4*)src, (uint2*)aHi, (uint2*)aLo, n4);
    };
    auto cvtB = [&](const float* w, int K, int N) {
        cvt_wt_t<<<dim3(N / 32, K / 32), dim3(32, 8)>>>(w, K, N, bHi, bLo);
    };

    detect_mask_kind<<<1, 32>>>((const unsigned int*)mask);

    // ---- x = MLP1(LN1(x))  (no residual) ----
    layernorm_k<<<ROWS, 256>>>(x, ln1_g, ln1_b, p_ln);
    cvtA(p_ln, (size_t)ROWS * H_DIM);
    cvtB(w_mlp1i, H_DIM, FF_DIM);
    run_mm(1, aHi, aLo, bHi, bLo, b_mlp1i, nullptr, p_ff, H_DIM, FF_DIM);
    cvtA(p_ff, (size_t)ROWS * FF_DIM);
    cvtB(w_mlp1o, FF_DIM, H_DIM);
    run_mm(0, aHi, aLo, bHi, bLo, b_mlp1o, nullptr, p_x, FF_DIM, H_DIM);

    // ---- q = l2(LN2(x) @ w_q + b_q) ----
    layernorm_k<<<ROWS, 256>>>(p_x, ln2_g, ln2_b, p_ln);
    cvtA(p_ln, (size_t)ROWS * H_DIM);
    cvtB(w_q, H_DIM, H_DIM);
    run_mm(0, aHi, aLo, bHi, bLo, b_q, nullptr, p_q, H_DIM, H_DIM);
    l2norm_k<<<(ROWS * NH_DIM) / 8, 256>>>(p_q, ROWS * NH_DIM);

    // ---- kv = mem @ w_kv + b_kv ; l2 over 128-wide segments ----
    cvtA(mem, (size_t)MROWS * H_DIM);
    cvtB(w_kv, H_DIM, 2 * H_DIM);
    run_mm(0, aHi, aLo, bHi, bLo, b_kv, nullptr, p_kv, H_DIM, 2 * H_DIM);
    l2norm_k<<<(MROWS * NH_DIM * 2) / 8, 256>>>(p_kv, MROWS * NH_DIM * 2);

    // ---- attention ----
    gemm_nt_scores<<<dim3(M_DIM / 128, S_DIM / 128, NBH), 256>>>(p_q, p_kv, mask, p_sc);
    softmax_k<<<NBH * S_DIM, 256>>>(p_sc);
    gemm_nn<0><<<dim3(1, S_DIM / 128, NBH), 256>>>(
        p_sc, p_kv + D_DIM, nullptr, nullptr, p_ctx,
        S_DIM, D_DIM, M_DIM,
        M_DIM, B_DIM * 2 * H_DIM, B_DIM * H_DIM, 0,
        (long long)S_DIM * M_DIM, 2 * D_DIM, D_DIM, 0);

    // ---- x = x + ctx @ w_dense + b_dense ----
    cvtA(p_ctx, (size_t)ROWS * H_DIM);
    cvtB(w_dense, H_DIM, H_DIM);
    run_mm(0, aHi, aLo, bHi, bLo, b_dense, p_x, p_x, H_DIM, H_DIM);

    // ---- out = x + MLP2(LN3(x)) ----
    layernorm_k<<<ROWS, 256>>>(p_x, ln3_g, ln3_b, p_ln);
    cvtA(p_ln, (size_t)ROWS * H_DIM);
    cvtB(w_mlp2i, H_DIM, FF_DIM);
    run_mm(1, aHi, aLo, bHi, bLo, b_mlp2i, nullptr, p_ff, H_DIM, FF_DIM);
    cvtA(p_ff, (size_t)ROWS * FF_DIM);
    cvtB(w_mlp2o, FF_DIM, H_DIM);
    run_mm(0, aHi, aLo, bHi, bLo, b_mlp2o, p_x, out, FF_DIM, H_DIM);
}